// round 1
// baseline (speedup 1.0000x reference)
#include <cuda_runtime.h>
#include <cstdint>

// ---------------------------------------------------------------------------
// DiGCN_IB_Sum: 3 stacked inception blocks.
// Block: out = x@Wln + (A1 x)@Wc1 + (A2 x)@Wc2 + (bln+bc1+bc2)
// (scatter commuted before the dense GEMM: A(xW) == (Ax)W)
// ---------------------------------------------------------------------------

#define NMAX 100000
#define F 128

// scratch (device globals; no cudaMalloc allowed)
__device__ float g_s1[(size_t)NMAX * F];
__device__ float g_s2[(size_t)NMAX * F];
__device__ float g_x1[(size_t)NMAX * F];
__device__ float g_x2[(size_t)NMAX * F];

// ---------------------------------------------------------------------------
__global__ void zero_kernel(float4* __restrict__ p, int n4) {
    int i = blockIdx.x * blockDim.x + threadIdx.x;
    int stride = gridDim.x * blockDim.x;
    float4 z = make_float4(0.f, 0.f, 0.f, 0.f);
    for (; i < n4; i += stride) p[i] = z;
}

// ---------------------------------------------------------------------------
// SpMM scatter: out[dst] += w * x[src], one warp per edge, float4 per lane.
__global__ void __launch_bounds__(256) spmm_scatter(
    const float* __restrict__ x,
    const int* __restrict__ src,
    const int* __restrict__ dst,
    const float* __restrict__ ew,
    float* __restrict__ out,
    int E)
{
    int warp = (blockIdx.x * blockDim.x + threadIdx.x) >> 5;
    int lane = threadIdx.x & 31;
    if (warp >= E) return;

    int s = __ldg(src + warp);
    int d = __ldg(dst + warp);
    float w = __ldg(ew + warp);

    const float4* xr = reinterpret_cast<const float4*>(x + (size_t)s * F);
    float4 v = __ldg(xr + lane);
    v.x *= w; v.y *= w; v.z *= w; v.w *= w;

    float* o = out + (size_t)d * F + lane * 4;
    asm volatile("red.global.add.v4.f32 [%0], {%1, %2, %3, %4};"
                 :: "l"(o), "f"(v.x), "f"(v.y), "f"(v.z), "f"(v.w)
                 : "memory");
}

// ---------------------------------------------------------------------------
// Fused 3-source GEMM: C = A0@B0 + A1@B1 + A2@B2 + (b0+b1+b2)
// A*: [M,128] row-major, B*: [128,128] row-major (din x dout), C: [M,128]
// blocktile 128x128, 256 threads, 8x8 per-thread microtile, KC=8.
__global__ void __launch_bounds__(256) gemm3_kernel(
    const float* __restrict__ A0, const float* __restrict__ A1, const float* __restrict__ A2,
    const float* __restrict__ B0, const float* __restrict__ B1, const float* __restrict__ B2,
    const float* __restrict__ b0, const float* __restrict__ b1, const float* __restrict__ b2,
    float* __restrict__ C, int M)
{
    __shared__ float As[8][132];   // [k][m], padded
    __shared__ float Bs[8][128];   // [k][n]

    const int tid  = threadIdx.x;
    const int row0 = blockIdx.x * 128;

    const int tm = (tid >> 4) << 3;   // 0..120
    const int tn = (tid & 15) << 3;   // 0..120

    // A loader coords: thread -> (row lr, 4 cols at lc)
    const int lr = tid >> 1;
    const int lc = (tid & 1) * 4;
    // B loader coords: thread -> (row br, 4 cols at bc)
    const int br = tid >> 5;
    const int bc = (tid & 31) * 4;

    float acc[8][8];
#pragma unroll
    for (int i = 0; i < 8; i++)
#pragma unroll
        for (int j = 0; j < 8; j++) acc[i][j] = 0.f;

    const float* Alist[3] = {A0, A1, A2};
    const float* Blist[3] = {B0, B1, B2};

    const bool a_row_ok = (row0 + lr) < M;

    for (int s = 0; s < 3; s++) {
        const float* A = Alist[s] + (size_t)row0 * F;
        const float* B = Blist[s];

#pragma unroll 1
        for (int kk = 0; kk < F; kk += 8) {
            float4 av = make_float4(0.f, 0.f, 0.f, 0.f);
            if (a_row_ok)
                av = *reinterpret_cast<const float4*>(A + (size_t)lr * F + kk + lc);
            As[lc + 0][lr] = av.x;
            As[lc + 1][lr] = av.y;
            As[lc + 2][lr] = av.z;
            As[lc + 3][lr] = av.w;

            *reinterpret_cast<float4*>(&Bs[br][bc]) =
                *reinterpret_cast<const float4*>(B + (size_t)(kk + br) * F + bc);

            __syncthreads();

#pragma unroll
            for (int k = 0; k < 8; k++) {
                float4 a0 = *reinterpret_cast<const float4*>(&As[k][tm]);
                float4 a1 = *reinterpret_cast<const float4*>(&As[k][tm + 4]);
                float4 bb0 = *reinterpret_cast<const float4*>(&Bs[k][tn]);
                float4 bb1 = *reinterpret_cast<const float4*>(&Bs[k][tn + 4]);
                float a[8] = {a0.x, a0.y, a0.z, a0.w, a1.x, a1.y, a1.z, a1.w};
                float b[8] = {bb0.x, bb0.y, bb0.z, bb0.w, bb1.x, bb1.y, bb1.z, bb1.w};
#pragma unroll
                for (int i = 0; i < 8; i++)
#pragma unroll
                    for (int j = 0; j < 8; j++)
                        acc[i][j] += a[i] * b[j];
            }
            __syncthreads();
        }
    }

    // epilogue: add summed bias, store
    float bias[8];
#pragma unroll
    for (int j = 0; j < 8; j++)
        bias[j] = __ldg(b0 + tn + j) + __ldg(b1 + tn + j) + __ldg(b2 + tn + j);

#pragma unroll
    for (int i = 0; i < 8; i++) {
        int m = row0 + tm + i;
        if (m < M) {
            float4 o0, o1;
            o0.x = acc[i][0] + bias[0];
            o0.y = acc[i][1] + bias[1];
            o0.z = acc[i][2] + bias[2];
            o0.w = acc[i][3] + bias[3];
            o1.x = acc[i][4] + bias[4];
            o1.y = acc[i][5] + bias[5];
            o1.z = acc[i][6] + bias[6];
            o1.w = acc[i][7] + bias[7];
            float* cp = C + (size_t)m * F + tn;
            *reinterpret_cast<float4*>(cp)     = o0;
            *reinterpret_cast<float4*>(cp + 4) = o1;
        }
    }
}

// ---------------------------------------------------------------------------
extern "C" void kernel_launch(void* const* d_in, const int* in_sizes, int n_in,
                              void* d_out, int out_size)
{
    const float* x   = (const float*)d_in[0];
    const int*   ei1 = (const int*)  d_in[1];
    const float* ea1 = (const float*)d_in[2];
    const int*   ei2 = (const int*)  d_in[3];
    const float* ea2 = (const float*)d_in[4];

    const float* W[3][3];
    const float* Bv[3][3];
    for (int blk = 0; blk < 3; blk++)
        for (int p = 0; p < 3; p++) {
            W[blk][p]  = (const float*)d_in[5 + blk * 6 + p * 2];
            Bv[blk][p] = (const float*)d_in[5 + blk * 6 + p * 2 + 1];
        }

    const int Nn = in_sizes[0] / F;
    const int E1 = in_sizes[1] / 2;
    const int E2 = in_sizes[3] / 2;

    float *s1, *s2, *x1, *x2;
    cudaGetSymbolAddress((void**)&s1, g_s1);
    cudaGetSymbolAddress((void**)&s2, g_s2);
    cudaGetSymbolAddress((void**)&x1, g_x1);
    cudaGetSymbolAddress((void**)&x2, g_x2);

    const int n4 = Nn * F / 4;
    const int zgrid = 1024;

    float* outs[3] = {x1, x2, (float*)d_out};
    const float* xin = x;

    for (int blk = 0; blk < 3; blk++) {
        zero_kernel<<<zgrid, 256>>>((float4*)s1, n4);
        zero_kernel<<<zgrid, 256>>>((float4*)s2, n4);

        spmm_scatter<<<(E1 + 7) / 8, 256>>>(xin, ei1, ei1 + E1, ea1, s1, E1);
        spmm_scatter<<<(E2 + 7) / 8, 256>>>(xin, ei2, ei2 + E2, ea2, s2, E2);

        gemm3_kernel<<<(Nn + 127) / 128, 256>>>(
            xin, s1, s2,
            W[blk][0], W[blk][1], W[blk][2],
            Bv[blk][0], Bv[blk][1], Bv[blk][2],
            outs[blk], Nn);

        xin = outs[blk];
    }
}

// round 2
// speedup vs baseline: 2.4551x; 2.4551x over previous
#include <cuda_runtime.h>
#include <cuda_bf16.h>
#include <cstdint>

#define NMAX 100000
#define EMAX 1700000
#define F 128

// ------------------------- device-global scratch ---------------------------
__device__ float g_s1[(size_t)NMAX * F];
__device__ float g_s2[(size_t)NMAX * F];
__device__ float g_x1[(size_t)NMAX * F];
__device__ float g_x2[(size_t)NMAX * F];
__device__ int   g_off1[NMAX], g_cur1[NMAX];
__device__ int   g_off2[NMAX], g_cur2[NMAX];
__device__ int   g_es1[EMAX],  g_es2[EMAX];
__device__ float g_ew1[EMAX],  g_ew2[EMAX];
__device__ int   g_part1[512], g_part2[512];

// ------------------------------- CSR build ---------------------------------
__global__ void zero_int_kernel(int* __restrict__ p, int n) {
    int i = blockIdx.x * blockDim.x + threadIdx.x;
    int stride = gridDim.x * blockDim.x;
    for (; i < n; i += stride) p[i] = 0;
}

__global__ void hist_kernel(const int* __restrict__ dst, int E, int* __restrict__ cnt) {
    int i = blockIdx.x * blockDim.x + threadIdx.x;
    int stride = gridDim.x * blockDim.x;
    for (; i < E; i += stride) atomicAdd(&cnt[dst[i]], 1);
}

// per-chunk exclusive scan (chunk = 512), chunk totals to partial[]
__global__ void __launch_bounds__(512) scanA_kernel(
    const int* __restrict__ cnt, int* __restrict__ off,
    int* __restrict__ partial, int N)
{
    __shared__ int sh[512];
    int t = threadIdx.x;
    int i = blockIdx.x * 512 + t;
    int v = (i < N) ? cnt[i] : 0;
    sh[t] = v;
    __syncthreads();
#pragma unroll
    for (int d = 1; d < 512; d <<= 1) {
        int u = (t >= d) ? sh[t - d] : 0;
        __syncthreads();
        sh[t] += u;
        __syncthreads();
    }
    if (i < N) off[i] = sh[t] - v;          // exclusive within chunk
    if (t == 511) partial[blockIdx.x] = sh[511];
}

// exclusive scan of chunk totals (single block)
__global__ void __launch_bounds__(512) scanB_kernel(int* __restrict__ partial, int NB) {
    __shared__ int sh[512];
    int t = threadIdx.x;
    int v = (t < NB) ? partial[t] : 0;
    sh[t] = v;
    __syncthreads();
#pragma unroll
    for (int d = 1; d < 512; d <<= 1) {
        int u = (t >= d) ? sh[t - d] : 0;
        __syncthreads();
        sh[t] += u;
        __syncthreads();
    }
    if (t < NB) partial[t] = sh[t] - v;     // exclusive
}

__global__ void scanC_kernel(int* __restrict__ off, const int* __restrict__ pbase,
                             int* __restrict__ cur, int N)
{
    int i = blockIdx.x * blockDim.x + threadIdx.x;
    int stride = gridDim.x * blockDim.x;
    for (; i < N; i += stride) {
        int o = off[i] + pbase[i >> 9];
        off[i] = o;
        cur[i] = o;
    }
}

__global__ void fill_kernel(const int* __restrict__ src, const int* __restrict__ dst,
                            const float* __restrict__ w, int E,
                            int* __restrict__ cur,
                            int* __restrict__ esrc, float* __restrict__ ewt)
{
    int i = blockIdx.x * blockDim.x + threadIdx.x;
    int stride = gridDim.x * blockDim.x;
    for (; i < E; i += stride) {
        int d = dst[i];
        int p = atomicAdd(&cur[d], 1);
        esrc[p] = src[i];
        ewt[p]  = w[i];
    }
}

// -------------------------- CSR gather SpMM ---------------------------------
// out[row] = sum_{edges of row} w * x[src] ; warp per row, float4 per lane.
__global__ void __launch_bounds__(256) spmm_gather(
    const float4* __restrict__ x4,
    const int* __restrict__ off, const int* __restrict__ end,
    const int* __restrict__ esrc, const float* __restrict__ ewt,
    float4* __restrict__ out4, int N)
{
    int warp = (blockIdx.x * blockDim.x + threadIdx.x) >> 5;
    int lane = threadIdx.x & 31;
    if (warp >= N) return;

    int beg = __ldg(off + warp);
    int en  = __ldg(end + warp);

    float4 acc = make_float4(0.f, 0.f, 0.f, 0.f);

    for (int j = beg; j < en; j += 32) {
        int cnt = min(32, en - j);
        int s = 0; float w = 0.f;
        if (lane < cnt) {
            s = __ldg(esrc + j + lane);
            w = __ldg(ewt + j + lane);
        }
        for (int t = 0; t < cnt; t++) {
            int   ss = __shfl_sync(0xffffffff, s, t);
            float ww = __shfl_sync(0xffffffff, w, t);
            float4 v = __ldg(x4 + (size_t)ss * 32 + lane);
            acc.x += ww * v.x;
            acc.y += ww * v.y;
            acc.z += ww * v.z;
            acc.w += ww * v.w;
        }
    }
    out4[(size_t)warp * 32 + lane] = acc;
}

// ---------------------- tensor-core fused 3-source GEMM ---------------------
// C = A0@B0 + A1@B1 + A2@B2 + (b0+b1+b2); fp32 in/out, bf16 hi/lo split (3 mma
// passes: hi*hi + hi*lo + lo*hi), fp32 accumulate. Block tile 128x128, 8 warps.

__device__ __forceinline__ void ldsm_x4(uint32_t* r, uint32_t addr) {
    asm volatile("ldmatrix.sync.aligned.m8n8.x4.shared.b16 {%0,%1,%2,%3}, [%4];"
                 : "=r"(r[0]), "=r"(r[1]), "=r"(r[2]), "=r"(r[3]) : "r"(addr));
}
__device__ __forceinline__ void ldsm_x2t(uint32_t& r0, uint32_t& r1, uint32_t addr) {
    asm volatile("ldmatrix.sync.aligned.m8n8.x2.trans.shared.b16 {%0,%1}, [%2];"
                 : "=r"(r0), "=r"(r1) : "r"(addr));
}
__device__ __forceinline__ void mma_bf16(float* d, const uint32_t* a, uint32_t b0, uint32_t b1) {
    asm volatile("mma.sync.aligned.m16n8k16.row.col.f32.bf16.bf16.f32 "
                 "{%0,%1,%2,%3}, {%4,%5,%6,%7}, {%8,%9}, {%0,%1,%2,%3};"
                 : "+f"(d[0]), "+f"(d[1]), "+f"(d[2]), "+f"(d[3])
                 : "r"(a[0]), "r"(a[1]), "r"(a[2]), "r"(a[3]), "r"(b0), "r"(b1));
}

#define A_STRIDE 24   // bf16 elems per A smem row (48B, conflict-free for ldmatrix)

__global__ void __launch_bounds__(256, 2) gemm3_tc(
    const float* __restrict__ A0, const float* __restrict__ A1, const float* __restrict__ A2,
    const float* __restrict__ B0, const float* __restrict__ B1, const float* __restrict__ B2,
    const float* __restrict__ b0, const float* __restrict__ b1, const float* __restrict__ b2,
    float* __restrict__ C, int M)
{
    __shared__ __nv_bfloat16 Ahi[128 * A_STRIDE];
    __shared__ __nv_bfloat16 Alo[128 * A_STRIDE];
    __shared__ __nv_bfloat16 Bhi[16 * 128];
    __shared__ __nv_bfloat16 Blo[16 * 128];
    __shared__ float bsum[128];

    const int tid  = threadIdx.x;
    const int lane = tid & 31;
    const int wid  = tid >> 5;
    const int row0 = blockIdx.x * 128;

    const int wm = (wid >> 1) * 32;   // warp m offset in tile (0,32,64,96)
    const int wn = (wid & 1) * 64;    // warp n offset in tile (0,64)

    // bias sums
    if (tid < 128) bsum[tid] = __ldg(b0 + tid) + __ldg(b1 + tid) + __ldg(b2 + tid);

    float acc[2][8][4];
#pragma unroll
    for (int mt = 0; mt < 2; mt++)
#pragma unroll
        for (int nt = 0; nt < 8; nt++)
#pragma unroll
            for (int q = 0; q < 4; q++) acc[mt][nt][q] = 0.f;

    // loader coords
    const int alr   = tid >> 1;          // A row 0..127
    const int akoff = (tid & 1) * 8;     // A k sub-offset 0/8
    const bool arow_ok = (row0 + alr) < M;
    const int bk = tid >> 4;             // B k row 0..15
    const int bj = tid & 15;             // B chunk 0..15 (8 cols)

    const uint32_t sAhi = (uint32_t)__cvta_generic_to_shared(Ahi);
    const uint32_t sAlo = (uint32_t)__cvta_generic_to_shared(Alo);
    const uint32_t sBhi = (uint32_t)__cvta_generic_to_shared(Bhi);
    const uint32_t sBlo = (uint32_t)__cvta_generic_to_shared(Blo);

    const float* Alist[3] = {A0, A1, A2};
    const float* Blist[3] = {B0, B1, B2};

    for (int s = 0; s < 3; s++) {
        const float* A = Alist[s];
        const float* B = Blist[s];

#pragma unroll 1
        for (int kk = 0; kk < 8; kk++) {
            const int k0 = kk * 16;
            __syncthreads();   // previous tiles fully consumed

            // ---- load + split A [128 x 16] ----
            {
                float f[8] = {0, 0, 0, 0, 0, 0, 0, 0};
                if (arow_ok) {
                    const float* ap = A + (size_t)(row0 + alr) * F + k0 + akoff;
                    float4 fa = *reinterpret_cast<const float4*>(ap);
                    float4 fb = *reinterpret_cast<const float4*>(ap + 4);
                    f[0] = fa.x; f[1] = fa.y; f[2] = fa.z; f[3] = fa.w;
                    f[4] = fb.x; f[5] = fb.y; f[6] = fb.z; f[7] = fb.w;
                }
                union { __nv_bfloat16 b[8]; uint4 u; } H, L;
#pragma unroll
                for (int q = 0; q < 8; q++) {
                    H.b[q] = __float2bfloat16(f[q]);
                    L.b[q] = __float2bfloat16(f[q] - __bfloat162float(H.b[q]));
                }
                *reinterpret_cast<uint4*>(&Ahi[alr * A_STRIDE + akoff]) = H.u;
                *reinterpret_cast<uint4*>(&Alo[alr * A_STRIDE + akoff]) = L.u;
            }
            // ---- load + split B [16 x 128] with XOR chunk swizzle ----
            {
                const float* bp = B + (size_t)(k0 + bk) * F + bj * 8;
                float4 fa = *reinterpret_cast<const float4*>(bp);
                float4 fb = *reinterpret_cast<const float4*>(bp + 4);
                float f[8] = {fa.x, fa.y, fa.z, fa.w, fb.x, fb.y, fb.z, fb.w};
                union { __nv_bfloat16 b[8]; uint4 u; } H, L;
#pragma unroll
                for (int q = 0; q < 8; q++) {
                    H.b[q] = __float2bfloat16(f[q]);
                    L.b[q] = __float2bfloat16(f[q] - __bfloat162float(H.b[q]));
                }
                const int cpos = bk * 128 + ((bj ^ (bk & 7)) * 8);
                *reinterpret_cast<uint4*>(&Bhi[cpos]) = H.u;
                *reinterpret_cast<uint4*>(&Blo[cpos]) = L.u;
            }
            __syncthreads();

            // ---- fragments + mma ----
            uint32_t ahi[2][4], alo[2][4];
#pragma unroll
            for (int mt = 0; mt < 2; mt++) {
                const int rl = wm + mt * 16 + (lane & 15);
                const uint32_t aoff = (uint32_t)(rl * (A_STRIDE * 2)) + ((lane >> 4) << 4);
                ldsm_x4(ahi[mt], sAhi + aoff);
                ldsm_x4(alo[mt], sAlo + aoff);
            }
#pragma unroll
            for (int nt = 0; nt < 8; nt++) {
                const int kl = lane & 15;
                const int chunk = ((wn >> 3) + nt) ^ (kl & 7);
                const uint32_t boff = (uint32_t)(kl * 256) + (uint32_t)(chunk << 4);
                uint32_t bh0, bh1, bl0, bl1;
                ldsm_x2t(bh0, bh1, sBhi + boff);
                ldsm_x2t(bl0, bl1, sBlo + boff);
#pragma unroll
                for (int mt = 0; mt < 2; mt++) {
                    mma_bf16(acc[mt][nt], ahi[mt], bh0, bh1);
                    mma_bf16(acc[mt][nt], ahi[mt], bl0, bl1);
                    mma_bf16(acc[mt][nt], alo[mt], bh0, bh1);
                }
            }
        }
    }
    __syncthreads();

    // ---- epilogue: bias + store ----
    const int g = lane >> 2;
    const int t = lane & 3;
#pragma unroll
    for (int mt = 0; mt < 2; mt++) {
        const int r0 = row0 + wm + mt * 16 + g;
        const int r1 = r0 + 8;
#pragma unroll
        for (int nt = 0; nt < 8; nt++) {
            const int c0 = wn + nt * 8 + 2 * t;
            const float bs0 = bsum[c0], bs1 = bsum[c0 + 1];
            if (r0 < M) {
                float2 v = make_float2(acc[mt][nt][0] + bs0, acc[mt][nt][1] + bs1);
                *reinterpret_cast<float2*>(C + (size_t)r0 * F + c0) = v;
            }
            if (r1 < M) {
                float2 v = make_float2(acc[mt][nt][2] + bs0, acc[mt][nt][3] + bs1);
                *reinterpret_cast<float2*>(C + (size_t)r1 * F + c0) = v;
            }
        }
    }
}

// ------------------------------- launcher ----------------------------------
extern "C" void kernel_launch(void* const* d_in, const int* in_sizes, int n_in,
                              void* d_out, int out_size)
{
    const float* x   = (const float*)d_in[0];
    const int*   ei1 = (const int*)  d_in[1];
    const float* ea1 = (const float*)d_in[2];
    const int*   ei2 = (const int*)  d_in[3];
    const float* ea2 = (const float*)d_in[4];

    const float* W[3][3];
    const float* Bv[3][3];
    for (int blk = 0; blk < 3; blk++)
        for (int p = 0; p < 3; p++) {
            W[blk][p]  = (const float*)d_in[5 + blk * 6 + p * 2];
            Bv[blk][p] = (const float*)d_in[5 + blk * 6 + p * 2 + 1];
        }

    const int Nn = in_sizes[0] / F;
    const int E1 = in_sizes[1] / 2;
    const int E2 = in_sizes[3] / 2;

    float *s1, *s2, *x1, *x2;
    int *off1, *cur1, *off2, *cur2, *es1, *es2, *part1, *part2;
    float *ew1, *ew2;
    cudaGetSymbolAddress((void**)&s1, g_s1);
    cudaGetSymbolAddress((void**)&s2, g_s2);
    cudaGetSymbolAddress((void**)&x1, g_x1);
    cudaGetSymbolAddress((void**)&x2, g_x2);
    cudaGetSymbolAddress((void**)&off1, g_off1);
    cudaGetSymbolAddress((void**)&cur1, g_cur1);
    cudaGetSymbolAddress((void**)&off2, g_off2);
    cudaGetSymbolAddress((void**)&cur2, g_cur2);
    cudaGetSymbolAddress((void**)&es1, g_es1);
    cudaGetSymbolAddress((void**)&es2, g_es2);
    cudaGetSymbolAddress((void**)&ew1, g_ew1);
    cudaGetSymbolAddress((void**)&ew2, g_ew2);
    cudaGetSymbolAddress((void**)&part1, g_part1);
    cudaGetSymbolAddress((void**)&part2, g_part2);

    const int NB = (Nn + 511) / 512;

    // ---- CSR build (once; edges constant across blocks) ----
    zero_int_kernel<<<256, 256>>>(cur1, Nn);
    zero_int_kernel<<<256, 256>>>(cur2, Nn);
    hist_kernel<<<1024, 256>>>(ei1 + E1, E1, cur1);
    hist_kernel<<<1024, 256>>>(ei2 + E2, E2, cur2);
    scanA_kernel<<<NB, 512>>>(cur1, off1, part1, Nn);
    scanA_kernel<<<NB, 512>>>(cur2, off2, part2, Nn);
    scanB_kernel<<<1, 512>>>(part1, NB);
    scanB_kernel<<<1, 512>>>(part2, NB);
    scanC_kernel<<<256, 256>>>(off1, part1, cur1, Nn);
    scanC_kernel<<<256, 256>>>(off2, part2, cur2, Nn);
    fill_kernel<<<1024, 256>>>(ei1, ei1 + E1, ea1, E1, cur1, es1, ew1);
    fill_kernel<<<1024, 256>>>(ei2, ei2 + E2, ea2, E2, cur2, es2, ew2);
    // after fill: cur[i] == off[i] + degree(i) == row end

    float* outs[3] = {x1, x2, (float*)d_out};
    const float* xin = x;
    const int sgrid = (Nn + 7) / 8;          // warp per row, 8 warps/block
    const int ggrid = (Nn + 127) / 128;

    for (int blk = 0; blk < 3; blk++) {
        spmm_gather<<<sgrid, 256>>>((const float4*)xin, off1, cur1, es1, ew1,
                                    (float4*)s1, Nn);
        spmm_gather<<<sgrid, 256>>>((const float4*)xin, off2, cur2, es2, ew2,
                                    (float4*)s2, Nn);
        gemm3_tc<<<ggrid, 256>>>(
            xin, s1, s2,
            W[blk][0], W[blk][1], W[blk][2],
            Bv[blk][0], Bv[blk][1], Bv[blk][2],
            outs[blk], Nn);
        xin = outs[blk];
    }
}

// round 3
// speedup vs baseline: 2.6671x; 1.0863x over previous
#include <cuda_runtime.h>
#include <cuda_bf16.h>
#include <cstdint>

#define NMAX 100000
#define EMAX 1700000
#define F 128

// ------------------------- device-global scratch ---------------------------
__device__ float g_s1[(size_t)NMAX * F];
__device__ float g_s2[(size_t)NMAX * F];
__device__ float g_x1[(size_t)NMAX * F];
__device__ float g_x2[(size_t)NMAX * F];
__device__ int   g_off1[NMAX], g_cur1[NMAX];
__device__ int   g_off2[NMAX], g_cur2[NMAX];
__device__ int2  g_e1[EMAX], g_e2[EMAX];     // interleaved {src, w-bits}
__device__ int   g_part1[512], g_part2[512];

// ------------------------------- CSR build ---------------------------------
__global__ void hist_kernel(const int* __restrict__ dst, int E, int* __restrict__ cnt) {
    int i = blockIdx.x * blockDim.x + threadIdx.x;
    int stride = gridDim.x * blockDim.x;
    for (; i < E; i += stride) atomicAdd(&cnt[dst[i]], 1);
}

// per-chunk exclusive scan (chunk = 512), chunk totals to partial[]
__global__ void __launch_bounds__(512) scanA_kernel(
    const int* __restrict__ cnt, int* __restrict__ off,
    int* __restrict__ partial, int N)
{
    __shared__ int sh[512];
    int t = threadIdx.x;
    int i = blockIdx.x * 512 + t;
    int v = (i < N) ? cnt[i] : 0;
    sh[t] = v;
    __syncthreads();
#pragma unroll
    for (int d = 1; d < 512; d <<= 1) {
        int u = (t >= d) ? sh[t - d] : 0;
        __syncthreads();
        sh[t] += u;
        __syncthreads();
    }
    if (i < N) off[i] = sh[t] - v;
    if (t == 511) partial[blockIdx.x] = sh[511];
}

__global__ void __launch_bounds__(512) scanB_kernel(int* __restrict__ partial, int NB) {
    __shared__ int sh[512];
    int t = threadIdx.x;
    int v = (t < NB) ? partial[t] : 0;
    sh[t] = v;
    __syncthreads();
#pragma unroll
    for (int d = 1; d < 512; d <<= 1) {
        int u = (t >= d) ? sh[t - d] : 0;
        __syncthreads();
        sh[t] += u;
        __syncthreads();
    }
    if (t < NB) partial[t] = sh[t] - v;
}

__global__ void scanC_kernel(int* __restrict__ off, const int* __restrict__ pbase,
                             int* __restrict__ cur, int N)
{
    int i = blockIdx.x * blockDim.x + threadIdx.x;
    int stride = gridDim.x * blockDim.x;
    for (; i < N; i += stride) {
        int o = off[i] + pbase[i >> 9];
        off[i] = o;
        cur[i] = o;
    }
}

__global__ void fill_kernel(const int* __restrict__ src, const int* __restrict__ dst,
                            const float* __restrict__ w, int E,
                            int* __restrict__ cur, int2* __restrict__ edges)
{
    int i = blockIdx.x * blockDim.x + threadIdx.x;
    int stride = gridDim.x * blockDim.x;
    for (; i < E; i += stride) {
        int d = dst[i];
        int p = atomicAdd(&cur[d], 1);
        edges[p] = make_int2(src[i], __float_as_int(w[i]));
    }
}

// -------------------------- CSR gather SpMM ---------------------------------
// out[row] = sum_{edges} w * x[src]; warp per row, float4 per lane, MLP=4.
__global__ void __launch_bounds__(256) spmm_gather(
    const float4* __restrict__ x4,
    const int* __restrict__ off, const int* __restrict__ end,
    const int2* __restrict__ edges,
    float4* __restrict__ out4, int N)
{
    int warp = (blockIdx.x * blockDim.x + threadIdx.x) >> 5;
    int lane = threadIdx.x & 31;
    if (warp >= N) return;

    int beg = __ldg(off + warp);
    int en  = __ldg(end + warp);

    float4 acc = make_float4(0.f, 0.f, 0.f, 0.f);

    for (int j = beg; j < en; j += 32) {
        int cnt = min(32, en - j);
        int2 e = make_int2(0, 0);
        if (lane < cnt) e = __ldg(edges + j + lane);

        int t = 0;
        for (; t + 4 <= cnt; t += 4) {
            int s0 = __shfl_sync(0xffffffffu, e.x, t);
            int s1 = __shfl_sync(0xffffffffu, e.x, t + 1);
            int s2 = __shfl_sync(0xffffffffu, e.x, t + 2);
            int s3 = __shfl_sync(0xffffffffu, e.x, t + 3);
            float w0 = __int_as_float(__shfl_sync(0xffffffffu, e.y, t));
            float w1 = __int_as_float(__shfl_sync(0xffffffffu, e.y, t + 1));
            float w2 = __int_as_float(__shfl_sync(0xffffffffu, e.y, t + 2));
            float w3 = __int_as_float(__shfl_sync(0xffffffffu, e.y, t + 3));
            float4 v0 = __ldg(x4 + (size_t)s0 * 32 + lane);
            float4 v1 = __ldg(x4 + (size_t)s1 * 32 + lane);
            float4 v2 = __ldg(x4 + (size_t)s2 * 32 + lane);
            float4 v3 = __ldg(x4 + (size_t)s3 * 32 + lane);
            acc.x += w0 * v0.x; acc.y += w0 * v0.y; acc.z += w0 * v0.z; acc.w += w0 * v0.w;
            acc.x += w1 * v1.x; acc.y += w1 * v1.y; acc.z += w1 * v1.z; acc.w += w1 * v1.w;
            acc.x += w2 * v2.x; acc.y += w2 * v2.y; acc.z += w2 * v2.z; acc.w += w2 * v2.w;
            acc.x += w3 * v3.x; acc.y += w3 * v3.y; acc.z += w3 * v3.z; acc.w += w3 * v3.w;
        }
        for (; t < cnt; t++) {
            int   ss = __shfl_sync(0xffffffffu, e.x, t);
            float ww = __int_as_float(__shfl_sync(0xffffffffu, e.y, t));
            float4 v = __ldg(x4 + (size_t)ss * 32 + lane);
            acc.x += ww * v.x; acc.y += ww * v.y; acc.z += ww * v.z; acc.w += ww * v.w;
        }
    }
    out4[(size_t)warp * 32 + lane] = acc;
}

// ---------------------- tensor-core fused 3-source GEMM ---------------------
__device__ __forceinline__ void ldsm_x4(uint32_t* r, uint32_t addr) {
    asm volatile("ldmatrix.sync.aligned.m8n8.x4.shared.b16 {%0,%1,%2,%3}, [%4];"
                 : "=r"(r[0]), "=r"(r[1]), "=r"(r[2]), "=r"(r[3]) : "r"(addr));
}
__device__ __forceinline__ void ldsm_x2t(uint32_t& r0, uint32_t& r1, uint32_t addr) {
    asm volatile("ldmatrix.sync.aligned.m8n8.x2.trans.shared.b16 {%0,%1}, [%2];"
                 : "=r"(r0), "=r"(r1) : "r"(addr));
}
__device__ __forceinline__ void mma_bf16(float* d, const uint32_t* a, uint32_t b0, uint32_t b1) {
    asm volatile("mma.sync.aligned.m16n8k16.row.col.f32.bf16.bf16.f32 "
                 "{%0,%1,%2,%3}, {%4,%5,%6,%7}, {%8,%9}, {%0,%1,%2,%3};"
                 : "+f"(d[0]), "+f"(d[1]), "+f"(d[2]), "+f"(d[3])
                 : "r"(a[0]), "r"(a[1]), "r"(a[2]), "r"(a[3]), "r"(b0), "r"(b1));
}

#define A_STRIDE 24

__global__ void __launch_bounds__(256, 2) gemm3_tc(
    const float* __restrict__ A0, const float* __restrict__ A1, const float* __restrict__ A2,
    const float* __restrict__ B0, const float* __restrict__ B1, const float* __restrict__ B2,
    const float* __restrict__ b0, const float* __restrict__ b1, const float* __restrict__ b2,
    float* __restrict__ C, int M)
{
    __shared__ __nv_bfloat16 Ahi[128 * A_STRIDE];
    __shared__ __nv_bfloat16 Alo[128 * A_STRIDE];
    __shared__ __nv_bfloat16 Bhi[16 * 128];
    __shared__ __nv_bfloat16 Blo[16 * 128];
    __shared__ float bsum[128];

    const int tid  = threadIdx.x;
    const int lane = tid & 31;
    const int wid  = tid >> 5;
    const int row0 = blockIdx.x * 128;

    const int wm = (wid >> 1) * 32;
    const int wn = (wid & 1) * 64;

    if (tid < 128) bsum[tid] = __ldg(b0 + tid) + __ldg(b1 + tid) + __ldg(b2 + tid);

    float acc[2][8][4];
#pragma unroll
    for (int mt = 0; mt < 2; mt++)
#pragma unroll
        for (int nt = 0; nt < 8; nt++)
#pragma unroll
            for (int q = 0; q < 4; q++) acc[mt][nt][q] = 0.f;

    const int alr   = tid >> 1;
    const int akoff = (tid & 1) * 8;
    const bool arow_ok = (row0 + alr) < M;
    const int bk = tid >> 4;
    const int bj = tid & 15;

    const uint32_t sAhi = (uint32_t)__cvta_generic_to_shared(Ahi);
    const uint32_t sAlo = (uint32_t)__cvta_generic_to_shared(Alo);
    const uint32_t sBhi = (uint32_t)__cvta_generic_to_shared(Bhi);
    const uint32_t sBlo = (uint32_t)__cvta_generic_to_shared(Blo);

    const float* Alist[3] = {A0, A1, A2};
    const float* Blist[3] = {B0, B1, B2};

    for (int s = 0; s < 3; s++) {
        const float* A = Alist[s];
        const float* B = Blist[s];

#pragma unroll 1
        for (int kk = 0; kk < 8; kk++) {
            const int k0 = kk * 16;
            __syncthreads();

            {
                float f[8] = {0, 0, 0, 0, 0, 0, 0, 0};
                if (arow_ok) {
                    const float* ap = A + (size_t)(row0 + alr) * F + k0 + akoff;
                    float4 fa = *reinterpret_cast<const float4*>(ap);
                    float4 fb = *reinterpret_cast<const float4*>(ap + 4);
                    f[0] = fa.x; f[1] = fa.y; f[2] = fa.z; f[3] = fa.w;
                    f[4] = fb.x; f[5] = fb.y; f[6] = fb.z; f[7] = fb.w;
                }
                union { __nv_bfloat16 b[8]; uint4 u; } H, L;
#pragma unroll
                for (int q = 0; q < 8; q++) {
                    H.b[q] = __float2bfloat16(f[q]);
                    L.b[q] = __float2bfloat16(f[q] - __bfloat162float(H.b[q]));
                }
                *reinterpret_cast<uint4*>(&Ahi[alr * A_STRIDE + akoff]) = H.u;
                *reinterpret_cast<uint4*>(&Alo[alr * A_STRIDE + akoff]) = L.u;
            }
            {
                const float* bp = B + (size_t)(k0 + bk) * F + bj * 8;
                float4 fa = *reinterpret_cast<const float4*>(bp);
                float4 fb = *reinterpret_cast<const float4*>(bp + 4);
                float f[8] = {fa.x, fa.y, fa.z, fa.w, fb.x, fb.y, fb.z, fb.w};
                union { __nv_bfloat16 b[8]; uint4 u; } H, L;
#pragma unroll
                for (int q = 0; q < 8; q++) {
                    H.b[q] = __float2bfloat16(f[q]);
                    L.b[q] = __float2bfloat16(f[q] - __bfloat162float(H.b[q]));
                }
                const int cpos = bk * 128 + ((bj ^ (bk & 7)) * 8);
                *reinterpret_cast<uint4*>(&Bhi[cpos]) = H.u;
                *reinterpret_cast<uint4*>(&Blo[cpos]) = L.u;
            }
            __syncthreads();

            uint32_t ahi[2][4], alo[2][4];
#pragma unroll
            for (int mt = 0; mt < 2; mt++) {
                const int rl = wm + mt * 16 + (lane & 15);
                const uint32_t aoff = (uint32_t)(rl * (A_STRIDE * 2)) + ((lane >> 4) << 4);
                ldsm_x4(ahi[mt], sAhi + aoff);
                ldsm_x4(alo[mt], sAlo + aoff);
            }
#pragma unroll
            for (int nt = 0; nt < 8; nt++) {
                const int kl = lane & 15;
                const int chunk = ((wn >> 3) + nt) ^ (kl & 7);
                const uint32_t boff = (uint32_t)(kl * 256) + (uint32_t)(chunk << 4);
                uint32_t bh0, bh1, bl0, bl1;
                ldsm_x2t(bh0, bh1, sBhi + boff);
                ldsm_x2t(bl0, bl1, sBlo + boff);
#pragma unroll
                for (int mt = 0; mt < 2; mt++) {
                    mma_bf16(acc[mt][nt], ahi[mt], bh0, bh1);
                    mma_bf16(acc[mt][nt], ahi[mt], bl0, bl1);
                    mma_bf16(acc[mt][nt], alo[mt], bh0, bh1);
                }
            }
        }
    }
    __syncthreads();

    const int g = lane >> 2;
    const int t = lane & 3;
#pragma unroll
    for (int mt = 0; mt < 2; mt++) {
        const int r0 = row0 + wm + mt * 16 + g;
        const int r1 = r0 + 8;
#pragma unroll
        for (int nt = 0; nt < 8; nt++) {
            const int c0 = wn + nt * 8 + 2 * t;
            const float bs0 = bsum[c0], bs1 = bsum[c0 + 1];
            if (r0 < M) {
                float2 v = make_float2(acc[mt][nt][0] + bs0, acc[mt][nt][1] + bs1);
                *reinterpret_cast<float2*>(C + (size_t)r0 * F + c0) = v;
            }
            if (r1 < M) {
                float2 v = make_float2(acc[mt][nt][2] + bs0, acc[mt][nt][3] + bs1);
                *reinterpret_cast<float2*>(C + (size_t)r1 * F + c0) = v;
            }
        }
    }
}

// ------------------------------- launcher ----------------------------------
extern "C" void kernel_launch(void* const* d_in, const int* in_sizes, int n_in,
                              void* d_out, int out_size)
{
    const float* x   = (const float*)d_in[0];
    const int*   ei1 = (const int*)  d_in[1];
    const float* ea1 = (const float*)d_in[2];
    const int*   ei2 = (const int*)  d_in[3];
    const float* ea2 = (const float*)d_in[4];

    const float* W[3][3];
    const float* Bv[3][3];
    for (int blk = 0; blk < 3; blk++)
        for (int p = 0; p < 3; p++) {
            W[blk][p]  = (const float*)d_in[5 + blk * 6 + p * 2];
            Bv[blk][p] = (const float*)d_in[5 + blk * 6 + p * 2 + 1];
        }

    const int Nn = in_sizes[0] / F;
    const int E1 = in_sizes[1] / 2;
    const int E2 = in_sizes[3] / 2;

    float *s1, *s2, *x1, *x2;
    int *off1, *cur1, *off2, *cur2, *part1, *part2;
    int2 *e1, *e2;
    cudaGetSymbolAddress((void**)&s1, g_s1);
    cudaGetSymbolAddress((void**)&s2, g_s2);
    cudaGetSymbolAddress((void**)&x1, g_x1);
    cudaGetSymbolAddress((void**)&x2, g_x2);
    cudaGetSymbolAddress((void**)&off1, g_off1);
    cudaGetSymbolAddress((void**)&cur1, g_cur1);
    cudaGetSymbolAddress((void**)&off2, g_off2);
    cudaGetSymbolAddress((void**)&cur2, g_cur2);
    cudaGetSymbolAddress((void**)&e1, g_e1);
    cudaGetSymbolAddress((void**)&e2, g_e2);
    cudaGetSymbolAddress((void**)&part1, g_part1);
    cudaGetSymbolAddress((void**)&part2, g_part2);

    const int NB = (Nn + 511) / 512;

    // ---- CSR build (once; edges constant across blocks) ----
    cudaMemsetAsync(cur1, 0, Nn * sizeof(int), 0);
    cudaMemsetAsync(cur2, 0, Nn * sizeof(int), 0);
    hist_kernel<<<1024, 256>>>(ei1 + E1, E1, cur1);
    hist_kernel<<<1024, 256>>>(ei2 + E2, E2, cur2);
    scanA_kernel<<<NB, 512>>>(cur1, off1, part1, Nn);
    scanA_kernel<<<NB, 512>>>(cur2, off2, part2, Nn);
    scanB_kernel<<<1, 512>>>(part1, NB);
    scanB_kernel<<<1, 512>>>(part2, NB);
    scanC_kernel<<<256, 256>>>(off1, part1, cur1, Nn);
    scanC_kernel<<<256, 256>>>(off2, part2, cur2, Nn);
    fill_kernel<<<1024, 256>>>(ei1, ei1 + E1, ea1, E1, cur1, e1);
    fill_kernel<<<1024, 256>>>(ei2, ei2 + E2, ea2, E2, cur2, e2);
    // after fill: cur[i] == off[i] + degree(i) == row end

    float* outs[3] = {x1, x2, (float*)d_out};
    const float* xin = x;
    const int sgrid = (Nn + 7) / 8;
    const int ggrid = (Nn + 127) / 128;

    for (int blk = 0; blk < 3; blk++) {
        spmm_gather<<<sgrid, 256>>>((const float4*)xin, off1, cur1, e1,
                                    (float4*)s1, Nn);
        spmm_gather<<<sgrid, 256>>>((const float4*)xin, off2, cur2, e2,
                                    (float4*)s2, Nn);
        gemm3_tc<<<ggrid, 256>>>(
            xin, s1, s2,
            W[blk][0], W[blk][1], W[blk][2],
            Bv[blk][0], Bv[blk][1], Bv[blk][2],
            outs[blk], Nn);
        xin = outs[blk];
    }
}

// round 4
// speedup vs baseline: 2.9023x; 1.0882x over previous
#include <cuda_runtime.h>
#include <cuda_bf16.h>
#include <cstdint>

#define NMAX 100000
#define EMAX 1700000
#define F 128

// ------------------------- device-global scratch ---------------------------
__device__ float g_s1[(size_t)NMAX * F];
__device__ float g_s2[(size_t)NMAX * F];
__device__ float g_x1[(size_t)NMAX * F];
__device__ float g_x2[(size_t)NMAX * F];
__device__ int   g_off1[NMAX], g_cur1[NMAX];
__device__ int   g_off2[NMAX], g_cur2[NMAX];
__device__ int2  g_e1[EMAX], g_e2[EMAX];     // interleaved {src, w-bits}
__device__ int   g_part1[512], g_part2[512];

// ------------------------------- CSR build ---------------------------------
// dual-graph histogram in one launch
__global__ void hist_dual(const int* __restrict__ d1, int E1, int* __restrict__ c1,
                          const int* __restrict__ d2, int E2, int* __restrict__ c2)
{
    int i = blockIdx.x * blockDim.x + threadIdx.x;
    int stride = gridDim.x * blockDim.x;
    int total = E1 + E2;
    for (; i < total; i += stride) {
        if (i < E1) atomicAdd(&c1[d1[i]], 1);
        else        atomicAdd(&c2[d2[i - E1]], 1);
    }
}

// per-chunk exclusive scan (chunk = 512); blockIdx.y selects graph
__global__ void __launch_bounds__(512) scanA_kernel(
    const int* __restrict__ cnt1, int* __restrict__ off1, int* __restrict__ p1,
    const int* __restrict__ cnt2, int* __restrict__ off2, int* __restrict__ p2,
    int N)
{
    const int* cnt = blockIdx.y ? cnt2 : cnt1;
    int* off       = blockIdx.y ? off2 : off1;
    int* partial   = blockIdx.y ? p2   : p1;
    __shared__ int sh[512];
    int t = threadIdx.x;
    int i = blockIdx.x * 512 + t;
    int v = (i < N) ? cnt[i] : 0;
    sh[t] = v;
    __syncthreads();
#pragma unroll
    for (int d = 1; d < 512; d <<= 1) {
        int u = (t >= d) ? sh[t - d] : 0;
        __syncthreads();
        sh[t] += u;
        __syncthreads();
    }
    if (i < N) off[i] = sh[t] - v;
    if (t == 511) partial[blockIdx.x] = sh[511];
}

__global__ void __launch_bounds__(512) scanB_kernel(
    int* __restrict__ p1, int* __restrict__ p2, int NB)
{
    int* partial = blockIdx.x ? p2 : p1;
    __shared__ int sh[512];
    int t = threadIdx.x;
    int v = (t < NB) ? partial[t] : 0;
    sh[t] = v;
    __syncthreads();
#pragma unroll
    for (int d = 1; d < 512; d <<= 1) {
        int u = (t >= d) ? sh[t - d] : 0;
        __syncthreads();
        sh[t] += u;
        __syncthreads();
    }
    if (t < NB) partial[t] = sh[t] - v;
}

__global__ void scanC_kernel(int* __restrict__ off1, const int* __restrict__ p1,
                             int* __restrict__ cur1,
                             int* __restrict__ off2, const int* __restrict__ p2,
                             int* __restrict__ cur2, int N)
{
    int* off        = blockIdx.y ? off2 : off1;
    const int* pb   = blockIdx.y ? p2   : p1;
    int* cur        = blockIdx.y ? cur2 : cur1;
    int i = blockIdx.x * blockDim.x + threadIdx.x;
    int stride = gridDim.x * blockDim.x;
    for (; i < N; i += stride) {
        int o = off[i] + pb[i >> 9];
        off[i] = o;
        cur[i] = o;
    }
}

__global__ void fill_dual(
    const int* __restrict__ s1, const int* __restrict__ d1, const float* __restrict__ w1,
    int E1, int* __restrict__ c1, int2* __restrict__ eo1,
    const int* __restrict__ s2, const int* __restrict__ d2, const float* __restrict__ w2,
    int E2, int* __restrict__ c2, int2* __restrict__ eo2)
{
    int i = blockIdx.x * blockDim.x + threadIdx.x;
    int stride = gridDim.x * blockDim.x;
    int total = E1 + E2;
    for (; i < total; i += stride) {
        if (i < E1) {
            int p = atomicAdd(&c1[d1[i]], 1);
            eo1[p] = make_int2(s1[i], __float_as_int(w1[i]));
        } else {
            int k = i - E1;
            int p = atomicAdd(&c2[d2[k]], 1);
            eo2[p] = make_int2(s2[k], __float_as_int(w2[k]));
        }
    }
}

// -------------------------- CSR gather SpMM ---------------------------------
// out[row] = sum_{edges} w * x[src]; warp per row, float4 per lane, MLP=8,
// smem-staged edge metadata with zero-weight padding (no tail loop).
__global__ void __launch_bounds__(512) spmm_gather(
    const float4* __restrict__ x4,
    const int* __restrict__ off, const int* __restrict__ end,
    const int2* __restrict__ edges,
    float4* __restrict__ out4, int N)
{
    __shared__ int2 se[16][32];

    const int wid  = threadIdx.x >> 5;
    const int lane = threadIdx.x & 31;
    const int row  = blockIdx.x * 16 + wid;
    if (row >= N) return;

    const int beg = __ldg(off + row);
    const int en  = __ldg(end + row);

    float4 acc = make_float4(0.f, 0.f, 0.f, 0.f);

    for (int j = beg; j < en; j += 32) {
        const int cnt = min(32, en - j);
        int2 e = make_int2(0, 0);                 // w = 0.0f pad -> contributes 0
        if (lane < cnt) e = __ldg(edges + j + lane);
        se[wid][lane] = e;
        __syncwarp();

        const int cnt8 = (cnt + 7) & ~7;
#pragma unroll 1
        for (int t = 0; t < cnt8; t += 8) {
            float4 v[8];
            float  w[8];
#pragma unroll
            for (int u = 0; u < 8; u++) {
                int2 ee = se[wid][t + u];
                w[u] = __int_as_float(ee.y);
                v[u] = __ldg(x4 + (size_t)ee.x * 32 + lane);
            }
#pragma unroll
            for (int u = 0; u < 8; u++) {
                acc.x += w[u] * v[u].x;
                acc.y += w[u] * v[u].y;
                acc.z += w[u] * v[u].z;
                acc.w += w[u] * v[u].w;
            }
        }
        __syncwarp();
    }
    out4[(size_t)row * 32 + lane] = acc;
}

// ---------------------- tensor-core fused 3-source GEMM ---------------------
__device__ __forceinline__ void ldsm_x4(uint32_t* r, uint32_t addr) {
    asm volatile("ldmatrix.sync.aligned.m8n8.x4.shared.b16 {%0,%1,%2,%3}, [%4];"
                 : "=r"(r[0]), "=r"(r[1]), "=r"(r[2]), "=r"(r[3]) : "r"(addr));
}
__device__ __forceinline__ void ldsm_x2t(uint32_t& r0, uint32_t& r1, uint32_t addr) {
    asm volatile("ldmatrix.sync.aligned.m8n8.x2.trans.shared.b16 {%0,%1}, [%2];"
                 : "=r"(r0), "=r"(r1) : "r"(addr));
}
__device__ __forceinline__ void mma_bf16(float* d, const uint32_t* a, uint32_t b0, uint32_t b1) {
    asm volatile("mma.sync.aligned.m16n8k16.row.col.f32.bf16.bf16.f32 "
                 "{%0,%1,%2,%3}, {%4,%5,%6,%7}, {%8,%9}, {%0,%1,%2,%3};"
                 : "+f"(d[0]), "+f"(d[1]), "+f"(d[2]), "+f"(d[3])
                 : "r"(a[0]), "r"(a[1]), "r"(a[2]), "r"(a[3]), "r"(b0), "r"(b1));
}

#define A_STRIDE 24

__global__ void __launch_bounds__(256, 2) gemm3_tc(
    const float* __restrict__ A0, const float* __restrict__ A1, const float* __restrict__ A2,
    const float* __restrict__ B0, const float* __restrict__ B1, const float* __restrict__ B2,
    const float* __restrict__ b0, const float* __restrict__ b1, const float* __restrict__ b2,
    float* __restrict__ C, int M)
{
    __shared__ __nv_bfloat16 Ahi[128 * A_STRIDE];
    __shared__ __nv_bfloat16 Alo[128 * A_STRIDE];
    __shared__ __nv_bfloat16 Bhi[16 * 128];
    __shared__ __nv_bfloat16 Blo[16 * 128];
    __shared__ float bsum[128];

    const int tid  = threadIdx.x;
    const int lane = tid & 31;
    const int wid  = tid >> 5;
    const int row0 = blockIdx.x * 128;

    const int wm = (wid >> 1) * 32;
    const int wn = (wid & 1) * 64;

    if (tid < 128) bsum[tid] = __ldg(b0 + tid) + __ldg(b1 + tid) + __ldg(b2 + tid);

    float acc[2][8][4];
#pragma unroll
    for (int mt = 0; mt < 2; mt++)
#pragma unroll
        for (int nt = 0; nt < 8; nt++)
#pragma unroll
            for (int q = 0; q < 4; q++) acc[mt][nt][q] = 0.f;

    const int alr   = tid >> 1;
    const int akoff = (tid & 1) * 8;
    const bool arow_ok = (row0 + alr) < M;
    const int bk = tid >> 4;
    const int bj = tid & 15;

    const uint32_t sAhi = (uint32_t)__cvta_generic_to_shared(Ahi);
    const uint32_t sAlo = (uint32_t)__cvta_generic_to_shared(Alo);
    const uint32_t sBhi = (uint32_t)__cvta_generic_to_shared(Bhi);
    const uint32_t sBlo = (uint32_t)__cvta_generic_to_shared(Blo);

    const float* Alist[3] = {A0, A1, A2};
    const float* Blist[3] = {B0, B1, B2};

    for (int s = 0; s < 3; s++) {
        const float* A = Alist[s];
        const float* B = Blist[s];

#pragma unroll 1
        for (int kk = 0; kk < 8; kk++) {
            const int k0 = kk * 16;
            __syncthreads();

            {
                float f[8] = {0, 0, 0, 0, 0, 0, 0, 0};
                if (arow_ok) {
                    const float* ap = A + (size_t)(row0 + alr) * F + k0 + akoff;
                    float4 fa = *reinterpret_cast<const float4*>(ap);
                    float4 fb = *reinterpret_cast<const float4*>(ap + 4);
                    f[0] = fa.x; f[1] = fa.y; f[2] = fa.z; f[3] = fa.w;
                    f[4] = fb.x; f[5] = fb.y; f[6] = fb.z; f[7] = fb.w;
                }
                union { __nv_bfloat16 b[8]; uint4 u; } H, L;
#pragma unroll
                for (int q = 0; q < 8; q++) {
                    H.b[q] = __float2bfloat16(f[q]);
                    L.b[q] = __float2bfloat16(f[q] - __bfloat162float(H.b[q]));
                }
                *reinterpret_cast<uint4*>(&Ahi[alr * A_STRIDE + akoff]) = H.u;
                *reinterpret_cast<uint4*>(&Alo[alr * A_STRIDE + akoff]) = L.u;
            }
            {
                const float* bp = B + (size_t)(k0 + bk) * F + bj * 8;
                float4 fa = *reinterpret_cast<const float4*>(bp);
                float4 fb = *reinterpret_cast<const float4*>(bp + 4);
                float f[8] = {fa.x, fa.y, fa.z, fa.w, fb.x, fb.y, fb.z, fb.w};
                union { __nv_bfloat16 b[8]; uint4 u; } H, L;
#pragma unroll
                for (int q = 0; q < 8; q++) {
                    H.b[q] = __float2bfloat16(f[q]);
                    L.b[q] = __float2bfloat16(f[q] - __bfloat162float(H.b[q]));
                }
                const int cpos = bk * 128 + ((bj ^ (bk & 7)) * 8);
                *reinterpret_cast<uint4*>(&Bhi[cpos]) = H.u;
                *reinterpret_cast<uint4*>(&Blo[cpos]) = L.u;
            }
            __syncthreads();

            uint32_t ahi[2][4], alo[2][4];
#pragma unroll
            for (int mt = 0; mt < 2; mt++) {
                const int rl = wm + mt * 16 + (lane & 15);
                const uint32_t aoff = (uint32_t)(rl * (A_STRIDE * 2)) + ((lane >> 4) << 4);
                ldsm_x4(ahi[mt], sAhi + aoff);
                ldsm_x4(alo[mt], sAlo + aoff);
            }
#pragma unroll
            for (int nt = 0; nt < 8; nt++) {
                const int kl = lane & 15;
                const int chunk = ((wn >> 3) + nt) ^ (kl & 7);
                const uint32_t boff = (uint32_t)(kl * 256) + (uint32_t)(chunk << 4);
                uint32_t bh0, bh1, bl0, bl1;
                ldsm_x2t(bh0, bh1, sBhi + boff);
                ldsm_x2t(bl0, bl1, sBlo + boff);
#pragma unroll
                for (int mt = 0; mt < 2; mt++) {
                    mma_bf16(acc[mt][nt], ahi[mt], bh0, bh1);
                    mma_bf16(acc[mt][nt], ahi[mt], bl0, bl1);
                    mma_bf16(acc[mt][nt], alo[mt], bh0, bh1);
                }
            }
        }
    }
    __syncthreads();

    const int g = lane >> 2;
    const int t = lane & 3;
#pragma unroll
    for (int mt = 0; mt < 2; mt++) {
        const int r0 = row0 + wm + mt * 16 + g;
        const int r1 = r0 + 8;
#pragma unroll
        for (int nt = 0; nt < 8; nt++) {
            const int c0 = wn + nt * 8 + 2 * t;
            const float bs0 = bsum[c0], bs1 = bsum[c0 + 1];
            if (r0 < M) {
                float2 v = make_float2(acc[mt][nt][0] + bs0, acc[mt][nt][1] + bs1);
                *reinterpret_cast<float2*>(C + (size_t)r0 * F + c0) = v;
            }
            if (r1 < M) {
                float2 v = make_float2(acc[mt][nt][2] + bs0, acc[mt][nt][3] + bs1);
                *reinterpret_cast<float2*>(C + (size_t)r1 * F + c0) = v;
            }
        }
    }
}

// ------------------------------- launcher ----------------------------------
extern "C" void kernel_launch(void* const* d_in, const int* in_sizes, int n_in,
                              void* d_out, int out_size)
{
    const float* x   = (const float*)d_in[0];
    const int*   ei1 = (const int*)  d_in[1];
    const float* ea1 = (const float*)d_in[2];
    const int*   ei2 = (const int*)  d_in[3];
    const float* ea2 = (const float*)d_in[4];

    const float* W[3][3];
    const float* Bv[3][3];
    for (int blk = 0; blk < 3; blk++)
        for (int p = 0; p < 3; p++) {
            W[blk][p]  = (const float*)d_in[5 + blk * 6 + p * 2];
            Bv[blk][p] = (const float*)d_in[5 + blk * 6 + p * 2 + 1];
        }

    const int Nn = in_sizes[0] / F;
    const int E1 = in_sizes[1] / 2;
    const int E2 = in_sizes[3] / 2;

    float *s1, *s2, *x1, *x2;
    int *off1, *cur1, *off2, *cur2, *part1, *part2;
    int2 *e1, *e2;
    cudaGetSymbolAddress((void**)&s1, g_s1);
    cudaGetSymbolAddress((void**)&s2, g_s2);
    cudaGetSymbolAddress((void**)&x1, g_x1);
    cudaGetSymbolAddress((void**)&x2, g_x2);
    cudaGetSymbolAddress((void**)&off1, g_off1);
    cudaGetSymbolAddress((void**)&cur1, g_cur1);
    cudaGetSymbolAddress((void**)&off2, g_off2);
    cudaGetSymbolAddress((void**)&cur2, g_cur2);
    cudaGetSymbolAddress((void**)&e1, g_e1);
    cudaGetSymbolAddress((void**)&e2, g_e2);
    cudaGetSymbolAddress((void**)&part1, g_part1);
    cudaGetSymbolAddress((void**)&part2, g_part2);

    const int NB = (Nn + 511) / 512;

    // ---- CSR build (once; edges constant across blocks) ----
    cudaMemsetAsync(cur1, 0, Nn * sizeof(int), 0);
    cudaMemsetAsync(cur2, 0, Nn * sizeof(int), 0);
    hist_dual<<<2048, 256>>>(ei1 + E1, E1, cur1, ei2 + E2, E2, cur2);
    {
        dim3 gA(NB, 2);
        scanA_kernel<<<gA, 512>>>(cur1, off1, part1, cur2, off2, part2, Nn);
        scanB_kernel<<<2, 512>>>(part1, part2, NB);
        dim3 gC(256, 2);
        scanC_kernel<<<gC, 256>>>(off1, part1, cur1, off2, part2, cur2, Nn);
    }
    fill_dual<<<2048, 256>>>(ei1, ei1 + E1, ea1, E1, cur1, e1,
                             ei2, ei2 + E2, ea2, E2, cur2, e2);
    // after fill: cur[i] == off[i] + degree(i) == row end

    float* outs[3] = {x1, x2, (float*)d_out};
    const float* xin = x;
    const int sgrid = (Nn + 15) / 16;        // warp per row, 16 warps/block
    const int ggrid = (Nn + 127) / 128;

    for (int blk = 0; blk < 3; blk++) {
        spmm_gather<<<sgrid, 512>>>((const float4*)xin, off1, cur1, e1,
                                    (float4*)s1, Nn);
        spmm_gather<<<sgrid, 512>>>((const float4*)xin, off2, cur2, e2,
                                    (float4*)s2, Nn);
        gemm3_tc<<<ggrid, 256>>>(
            xin, s1, s2,
            W[blk][0], W[blk][1], W[blk][2],
            Bv[blk][0], Bv[blk][1], Bv[blk][2],
            outs[blk], Nn);
        xin = outs[blk];
    }
}